// round 2
// baseline (speedup 1.0000x reference)
#include <cuda_runtime.h>
#include <cstdint>

#define IN_DIM 128
#define HID    64
#define NPB    256          // nodes per block in K1 (1 node per thread)
#define HS_STRIDE 65        // padded shared stride for H tile (conflict-free reads)
#define K3N    512          // nodes per block in K3

// smem: w1s [128][64] packed (16B-aligned) + Hs [256][65]
#define SMEM_FLOATS (IN_DIM*HID + NPB*HS_STRIDE)
#define SMEM_BYTES  (SMEM_FLOATS * 4)

// ---------------- scratch (static device globals; no allocation) ----------------
__device__ float    g_s[1100032];      // per-node score, then exp value
__device__ float    g_denom[1048576];  // per-segment softmax denominator
__device__ unsigned g_maxu[1048576];   // per-segment max (order-preserving uint encoding)
__device__ int      g_is64;            // batch dtype flag

// ---------------- helpers ----------------
__device__ __forceinline__ unsigned enc_f(float f) {
    unsigned u = __float_as_uint(f);
    return (u & 0x80000000u) ? ~u : (u | 0x80000000u);
}
__device__ __forceinline__ float dec_f(unsigned u) {
    return (u & 0x80000000u) ? __uint_as_float(u & 0x7fffffffu) : __uint_as_float(~u);
}
__device__ __forceinline__ int getb(const void* bp, int i) {
    if (g_is64) return (int)((const long long*)bp)[i];
    return ((const int*)bp)[i];
}
__device__ __forceinline__ unsigned long long pack2(float x, float y) {
    unsigned long long r;
    asm("mov.b64 %0, {%1, %2};" : "=l"(r) : "r"(__float_as_uint(x)), "r"(__float_as_uint(y)));
    return r;
}
__device__ __forceinline__ float2 unpack2(unsigned long long v) {
    unsigned lo, hi;
    asm("mov.b64 {%0, %1}, %2;" : "=r"(lo), "=r"(hi) : "l"(v));
    return make_float2(__uint_as_float(lo), __uint_as_float(hi));
}
// packed f32x2 FMA (FFMA2) — 2x fp32 throughput vs scalar FFMA on sm_103a
#define FMA2(acc, a, b) asm("fma.rn.f32x2 %0, %1, %2, %0;" : "+l"(acc) : "l"(a), "l"(b))

// ---------------- K-detect: is batch int64 or int32? ----------------
__global__ void kdetect(const void* __restrict__ batch, int N, int G) {
    __shared__ int bad;
    if (threadIdx.x == 0) bad = 0;
    __syncthreads();
    const long long* b64 = (const long long*)batch;
    int half = N >> 1;
    int last = (half > 1) ? (half - 1) : 0;
    for (int t = threadIdx.x; t < 2048; t += 256) {
        long long idx = (long long)t * last / 2047;
        long long v = b64[idx];
        if (v < 0 || v >= (long long)G) bad = 1;   // benign race
    }
    __syncthreads();
    if (threadIdx.x == 0) g_is64 = bad ? 0 : 1;
}

// ---------------- K0: zero outputs + per-segment state ----------------
__global__ void k0(float* __restrict__ out, int outSize, int G) {
    int i = blockIdx.x * blockDim.x + threadIdx.x;
    if (i < outSize) out[i] = 0.f;
    if (i < G) { g_denom[i] = 0.f; g_maxu[i] = 0u; }
}

// ---------------- K1: s = w2 . tanh(H w1^T), + segment max ----------------
// 256 threads, 1 node/thread, 64 hid/thread in 32 f32x2 accumulators.
// H: 1 conflict-free scalar LDS per k (no amplification).
// w1: broadcast LDS.128 consumed directly as ulonglong2 (no pack MOVs).
__global__ __launch_bounds__(256, 2)
void k1(const float* __restrict__ H, const float* __restrict__ w1,
        const float* __restrict__ w2, const void* __restrict__ batch, int N) {
    extern __shared__ float sm[];
    float* w1s = sm;                       // [128][64], k-major, densely packed
    float* Hs  = sm + IN_DIM * HID;        // [256][HS_STRIDE]

    const int tid = threadIdx.x;
    const int n0  = blockIdx.x * NPB;
    const int gn  = n0 + tid;

    // transpose w1 [64][128] -> w1s[k*64+h] (coalesced global reads; one-time
    // 32-way smem write conflicts are negligible vs the main loop)
    for (int idx = tid; idx < HID * IN_DIM; idx += 256) {
        int h = idx >> 7, k = idx & 127;
        w1s[k * HID + h] = w1[idx];
    }

    unsigned long long acc[32];
#pragma unroll
    for (int g = 0; g < 32; ++g) acc[g] = 0ull;

    const float4* H4 = (const float4*)H;

    for (int pass = 0; pass < 2; pass++) {
        __syncthreads();
        // stage 256 nodes x 64 K-values of H (coalesced float4 global reads)
#pragma unroll
        for (int it = 0; it < 16; ++it) {
            int idx = it * 256 + tid;
            int row = idx >> 4, c4 = idx & 15;
            int g = n0 + row;
            float4 v = make_float4(0.f, 0.f, 0.f, 0.f);
            if (g < N) v = H4[(size_t)g * 32 + pass * 16 + c4];
            float* d = &Hs[row * HS_STRIDE + c4 * 4];
            d[0] = v.x; d[1] = v.y; d[2] = v.z; d[3] = v.w;
        }
        __syncthreads();

        const float* hrow = &Hs[tid * HS_STRIDE];
        const ulonglong2* wbase =
            (const ulonglong2*)(w1s + (size_t)pass * 64 * HID);
#pragma unroll 4
        for (int kk = 0; kk < 64; ++kk) {
            float hv = hrow[kk];
            unsigned long long hp = pack2(hv, hv);
            const ulonglong2* w = wbase + kk * (HID / 4);
#pragma unroll
            for (int g = 0; g < 16; ++g) {
                ulonglong2 ww = w[g];          // broadcast LDS.128
                FMA2(acc[2 * g],     hp, ww.x);
                FMA2(acc[2 * g + 1], hp, ww.y);
            }
        }
    }

    // epilogue: tanh + dot with w2 (entirely per-thread)
    float s = 0.f;
#pragma unroll
    for (int g = 0; g < 32; ++g) {
        float2 v = unpack2(acc[g]);
        s = fmaf(__ldg(&w2[2 * g]),     tanhf(v.x), s);
        s = fmaf(__ldg(&w2[2 * g + 1]), tanhf(v.y), s);
    }

    // store s, warp-segmented atomicMax into g_maxu (batch sorted)
    {
        bool act = gn < N;
        int b = act ? getb(batch, gn) : 0x7fffffff;
        if (act) g_s[gn] = s;
        unsigned em = act ? enc_f(s) : 0u;
        int lane = tid & 31;
#pragma unroll
        for (int d = 1; d < 32; d <<= 1) {
            unsigned v = __shfl_down_sync(0xffffffffu, em, d);
            int b2     = __shfl_down_sync(0xffffffffu, b, d);
            if ((lane + d) < 32 && b2 == b) em = em > v ? em : v;
        }
        int bprev = __shfl_up_sync(0xffffffffu, b, 1);
        if (act && (lane == 0 || bprev != b)) atomicMax(&g_maxu[b], em);
    }
}

// ---------------- K2: e = exp(s - m[b]); segment-sum denominators ----------------
__global__ void k2(const void* __restrict__ batch, int N) {
    int i = blockIdx.x * blockDim.x + threadIdx.x;
    bool act = i < N;
    int lane = threadIdx.x & 31;
    float e = 0.f;
    int b = 0x7fffffff;
    if (act) {
        b = getb(batch, i);
        float m = dec_f(g_maxu[b]);
        e = expf(g_s[i] - m);
        g_s[i] = e;
    }
#pragma unroll
    for (int d = 1; d < 32; d <<= 1) {
        float v = __shfl_down_sync(0xffffffffu, e, d);
        int b2  = __shfl_down_sync(0xffffffffu, b, d);
        if ((lane + d) < 32 && b2 == b) e += v;
    }
    int bprev = __shfl_up_sync(0xffffffffu, b, 1);
    if (act && (lane == 0 || bprev != b)) atomicAdd(&g_denom[b], e);
}

// ---------------- K3: out[b,:] += (e/denom[b]) * H[i,:] ----------------
// 256 threads = 8 warps; each warp owns 64 contiguous sorted nodes; each lane
// owns one float4 feature chunk (LDG.128, 512B/warp coalesced). Register
// accumulation per segment run, atomics only at segment boundaries.
__global__ __launch_bounds__(256)
void k3(const float* __restrict__ H, const void* __restrict__ batch,
        float* __restrict__ out, int N) {
    __shared__ float cf[K3N];
    __shared__ int   sg[K3N];
    const int tid = threadIdx.x;
    const int n0  = blockIdx.x * K3N;

    for (int t = tid; t < K3N; t += 256) {
        int i = n0 + t;
        if (i < N) {
            int b = getb(batch, i);
            sg[t] = b;
            cf[t] = g_s[i] / g_denom[b];
        } else {
            sg[t] = -1;
        }
    }
    __syncthreads();

    const int w    = tid >> 5;
    const int lane = tid & 31;
    const int base = w * 64;
    int cur = sg[base];
    if (cur < 0) return;

    const float4* H4 = (const float4*)H;
    float4 a = make_float4(0.f, 0.f, 0.f, 0.f);

    for (int t = 0; t < 64; ++t) {
        int b = sg[base + t];
        if (b < 0) break;
        if (b != cur) {
            float* o = &out[(size_t)cur * IN_DIM + lane * 4];
            atomicAdd(o + 0, a.x); atomicAdd(o + 1, a.y);
            atomicAdd(o + 2, a.z); atomicAdd(o + 3, a.w);
            a = make_float4(0.f, 0.f, 0.f, 0.f);
            cur = b;
        }
        float c = cf[base + t];                       // smem broadcast
        float4 h = __ldg(&H4[(size_t)(n0 + base + t) * 32 + lane]);
        a.x = fmaf(c, h.x, a.x); a.y = fmaf(c, h.y, a.y);
        a.z = fmaf(c, h.z, a.z); a.w = fmaf(c, h.w, a.w);
    }
    float* o = &out[(size_t)cur * IN_DIM + lane * 4];
    atomicAdd(o + 0, a.x); atomicAdd(o + 1, a.y);
    atomicAdd(o + 2, a.z); atomicAdd(o + 3, a.w);
}

// ---------------- launch ----------------
extern "C" void kernel_launch(void* const* d_in, const int* in_sizes, int n_in,
                              void* d_out, int out_size) {
    const float* H  = (const float*)d_in[0];
    const float* w1 = (const float*)d_in[1];
    const float* w2 = (const float*)d_in[2];
    const void*  batch = d_in[3];
    int N = in_sizes[0] / IN_DIM;
    int G = out_size / IN_DIM;
    float* out = (float*)d_out;

    cudaFuncSetAttribute(k1, cudaFuncAttributeMaxDynamicSharedMemorySize, SMEM_BYTES);

    kdetect<<<1, 256>>>(batch, N, G);
    int initN = out_size > G ? out_size : G;
    k0<<<(initN + 255) / 256, 256>>>(out, out_size, G);
    k1<<<(N + NPB - 1) / NPB, 256, SMEM_BYTES>>>(H, w1, w2, batch, N);
    k2<<<(N + 255) / 256, 256>>>(batch, N);
    k3<<<(N + K3N - 1) / K3N, 256>>>(H, batch, out, N);
}

// round 5
// speedup vs baseline: 1.3997x; 1.3997x over previous
#include <cuda_runtime.h>
#include <cstdint>

#define IN_DIM 128
#define HID    64
#define TILE_M 128
#define HS_STRIDE 132   // floats per smem H row (conflict-free for both access patterns)

// ---- shared memory layout (bytes) ----
#define SOFF_SPART 0                       // 4*128 floats = 2048
#define SOFF_CF    2048                    // 128 floats
#define SOFF_SG    2560                    // 128 ints
#define SOFF_H0    3072                    // 128*132*4 = 67584
#define SOFF_H1    70656
#define SMEM_TOTAL 138240

// ---------------- scratch ----------------
__device__ float g_denom[1048576];
__device__ int   g_is64;

__device__ __forceinline__ int getb(const void* bp, int i) {
    if (g_is64) return (int)((const long long*)bp)[i];
    return ((const int*)bp)[i];
}

// exact-tf32 split: hi = top 10 mantissa bits (valid tf32), lo = fp32 residual
__device__ __forceinline__ void split_tf32(float x, uint32_t& hi, uint32_t& lo) {
    uint32_t u = __float_as_uint(x) & 0xFFFFE000u;
    hi = u;
    lo = __float_as_uint(x - __uint_as_float(u));
}

__device__ __forceinline__ void mma8(float* acc, const uint32_t* a, uint32_t b0, uint32_t b1) {
    asm("mma.sync.aligned.m16n8k8.row.col.f32.tf32.tf32.f32 "
        "{%0,%1,%2,%3}, {%4,%5,%6,%7}, {%8,%9}, {%0,%1,%2,%3};"
        : "+f"(acc[0]), "+f"(acc[1]), "+f"(acc[2]), "+f"(acc[3])
        : "r"(a[0]), "r"(a[1]), "r"(a[2]), "r"(a[3]), "r"(b0), "r"(b1));
}

__device__ __forceinline__ float ftanh(float x) {
    float e2 = __expf(2.f * x);
    return 1.f - __fdividef(2.f, e2 + 1.f);
}

// ---------------- kdetect: batch dtype ----------------
__global__ void kdetect(const void* __restrict__ batch, int N, int G) {
    __shared__ int bad;
    if (threadIdx.x == 0) bad = 0;
    __syncthreads();
    const long long* b64 = (const long long*)batch;
    int half = N >> 1;
    int last = (half > 1) ? (half - 1) : 0;
    for (int t = threadIdx.x; t < 2048; t += 256) {
        long long idx = (long long)t * last / 2047;
        long long v = b64[idx];
        if (v < 0 || v >= (long long)G) bad = 1;
    }
    __syncthreads();
    if (threadIdx.x == 0) g_is64 = bad ? 0 : 1;
}

// ---------------- k0: zero out + denom ----------------
__global__ void k0(float* __restrict__ out, int outSize, int G) {
    int i = blockIdx.x * blockDim.x + threadIdx.x;
    if (i < outSize) out[i] = 0.f;
    if (i < G) g_denom[i] = 0.f;
}

// ---------------- fused: tf32 mma GEMM + tanh + score + exp + segment scatter ----------------
__global__ __launch_bounds__(256, 1)
void kfused(const float* __restrict__ H, const float* __restrict__ w1,
            const float* __restrict__ w2, const void* __restrict__ batch,
            float* __restrict__ out, int N) {
    extern __shared__ char smem[];
    float* spart = (float*)(smem + SOFF_SPART);   // [4][128]
    float* cf    = (float*)(smem + SOFF_CF);      // [128] numerators e
    int*   sg    = (int*)(smem + SOFF_SG);        // [128] segment ids

    const int tid   = threadIdx.x;
    const int w     = tid >> 5;          // warp 0..7
    const int lane  = tid & 31;
    const int g     = lane >> 2;         // group id 0..7
    const int c     = lane & 3;          // thread-in-group
    const int wsl   = w & 3;             // hid slice 0..3 (16 hid each)
    const int ogrp  = (w >> 2) * 8;      // octet base: warps 0-3 -> 0, 4-7 -> 8

    // ---- load w1 A-fragments (hi/lo), resident in registers for whole kernel ----
    uint32_t Ah[16][4], Al[16][4];
    {
        const int r0 = (16 * wsl + g) * IN_DIM;
        const int r1 = (16 * wsl + g + 8) * IN_DIM;
#pragma unroll
        for (int j = 0; j < 16; ++j) {
            split_tf32(__ldg(&w1[r0 + 8 * j + c]),     Ah[j][0], Al[j][0]);
            split_tf32(__ldg(&w1[r1 + 8 * j + c]),     Ah[j][1], Al[j][1]);
            split_tf32(__ldg(&w1[r0 + 8 * j + c + 4]), Ah[j][2], Al[j][2]);
            split_tf32(__ldg(&w1[r1 + 8 * j + c + 4]), Ah[j][3], Al[j][3]);
        }
    }
    const float w2a = __ldg(&w2[16 * wsl + g]);
    const float w2b = __ldg(&w2[16 * wsl + g + 8]);

    const long long T = ((long long)N + TILE_M - 1) / TILE_M;
    long long t = blockIdx.x;
    int buf = 0;

    auto prefetch = [&](long long tt, int bsel) {
        const char* base = (const char*)H + (unsigned long long)tt * TILE_M * IN_DIM * 4ull;
        char* dstb = smem + (bsel ? SOFF_H1 : SOFF_H0);
#pragma unroll
        for (int it = 0; it < 16; ++it) {
            int idx = it * 256 + tid;
            int row = idx >> 5, c4 = idx & 31;
            long long gn = tt * TILE_M + row;
            uint32_t d;
            asm("{ .reg .u64 tt; cvta.to.shared.u64 tt, %1; cvt.u32.u64 %0, tt; }"
                : "=r"(d) : "l"(dstb + row * (HS_STRIDE * 4) + c4 * 16));
            const char* s = base + (row * 512 + c4 * 16);
            int sz = (gn < N) ? 16 : 0;
            asm volatile("cp.async.cg.shared.global [%0], [%1], 16, %2;"
                         :: "r"(d), "l"(s), "r"(sz) : "memory");
        }
        asm volatile("cp.async.commit_group;" ::: "memory");
    };

    if (t < T) prefetch(t, 0);

    for (; t < T; t += gridDim.x) {
        asm volatile("cp.async.wait_group 0;" ::: "memory");
        __syncthreads();
        long long tn = t + gridDim.x;
        if (tn < T) prefetch(tn, buf ^ 1);

        const float* Hs = (const float*)(smem + (buf ? SOFF_H1 : SOFF_H0));

        // ---- per-octet: 48 mma (3-pass tf32) + tanh/w2 epilogue partials ----
#pragma unroll 1
        for (int o = 0; o < 8; ++o) {
            const int oct = ogrp + o;
            const float* hb = Hs + (8 * oct + g) * HS_STRIDE + c;
            float acc[4] = {0.f, 0.f, 0.f, 0.f};
#pragma unroll
            for (int j = 0; j < 16; ++j) {
                float r0 = hb[8 * j];
                float r1 = hb[8 * j + 4];
                uint32_t b0h, b0l, b1h, b1l;
                split_tf32(r0, b0h, b0l);
                split_tf32(r1, b1h, b1l);
                mma8(acc, Ah[j], b0h, b1h);
                mma8(acc, Al[j], b0h, b1h);
                mma8(acc, Ah[j], b0l, b1l);
            }
            // partial s for 2 nodes: sum over this thread's 2 hid rows
            float pe = fmaf(w2a, ftanh(acc[0]), w2b * ftanh(acc[2]));
            float po = fmaf(w2a, ftanh(acc[1]), w2b * ftanh(acc[3]));
#pragma unroll
            for (int m = 4; m <= 16; m <<= 1) {
                pe += __shfl_xor_sync(0xffffffffu, pe, m);
                po += __shfl_xor_sync(0xffffffffu, po, m);
            }
            if (g == 0) {
                spart[wsl * 128 + oct * 8 + 2 * c]     = pe;
                spart[wsl * 128 + oct * 8 + 2 * c + 1] = po;
            }
        }
        __syncthreads();

        // ---- combine hid slices, e = exp(s), segment denom ----
        if (tid < 128) {
            long long gn = t * TILE_M + tid;
            bool act = gn < N;
            float s = spart[tid] + spart[128 + tid] + spart[256 + tid] + spart[384 + tid];
            float e = act ? __expf(s) : 0.f;
            int b = act ? getb(batch, (int)gn) : -1;
            cf[tid] = e;
            sg[tid] = b;
            int bb = act ? b : 0x7fffffff;
            float es = e;
#pragma unroll
            for (int d = 1; d < 32; d <<= 1) {
                float v  = __shfl_down_sync(0xffffffffu, es, d);
                int   b2 = __shfl_down_sync(0xffffffffu, bb, d);
                if ((lane + d) < 32 && b2 == bb) es += v;
            }
            int bprev = __shfl_up_sync(0xffffffffu, bb, 1);
            if (act && (lane == 0 || bprev != bb)) atomicAdd(&g_denom[bb], es);
        }
        __syncthreads();

        // ---- scatter: 2 halves x 128 feats, run-accumulate over sorted nodes ----
        {
            const int f    = tid & 127;
            const int base = (tid >> 7) * 64;
            int cur = sg[base];
            if (cur >= 0) {
                float acc = 0.f;
#pragma unroll 4
                for (int j = 0; j < 64; ++j) {
                    int bj = sg[base + j];
                    if (bj < 0) break;
                    if (bj != cur) {
                        atomicAdd(&out[(size_t)cur * IN_DIM + f], acc);
                        acc = 0.f;
                        cur = bj;
                    }
                    acc = fmaf(cf[base + j], Hs[(base + j) * HS_STRIDE + f], acc);
                }
                atomicAdd(&out[(size_t)cur * IN_DIM + f], acc);
            }
        }
        buf ^= 1;
    }
}

// ---------------- final divide ----------------
__global__ void kfin(float* __restrict__ out, int outSize) {
    int i = blockIdx.x * blockDim.x + threadIdx.x;
    if (i < outSize) {
        float d = g_denom[i >> 7];
        out[i] = (d > 0.f) ? out[i] / d : 0.f;
    }
}

// ---------------- launch ----------------
extern "C" void kernel_launch(void* const* d_in, const int* in_sizes, int n_in,
                              void* d_out, int out_size) {
    const float* H  = (const float*)d_in[0];
    const float* w1 = (const float*)d_in[1];
    const float* w2 = (const float*)d_in[2];
    const void*  batch = d_in[3];
    int N = in_sizes[0] / IN_DIM;
    int G = out_size / IN_DIM;
    float* out = (float*)d_out;

    int sms = 148;
    cudaDeviceGetAttribute(&sms, cudaDevAttrMultiProcessorCount, 0);

    cudaFuncSetAttribute(kfused, cudaFuncAttributeMaxDynamicSharedMemorySize, SMEM_TOTAL);

    kdetect<<<1, 256>>>(batch, N, G);
    int initN = out_size > G ? out_size : G;
    k0<<<(initN + 255) / 256, 256>>>(out, out_size, G);
    kfused<<<sms, 256, SMEM_TOTAL>>>(H, w1, w2, batch, out, N);
    kfin<<<(out_size + 255) / 256, 256>>>(out, out_size);
}

// round 6
// speedup vs baseline: 2.2514x; 1.6085x over previous
#include <cuda_runtime.h>
#include <cstdint>

#define IN_DIM 128
#define HID    64
#define TILE_M 128

// ---- shared memory layout (bytes) ----
#define SOFF_SPART 0                       // 4*128 floats = 2048
#define SOFF_CF    2048                    // 128 floats
#define SOFF_SG    2560                    // 128 ints
#define SOFF_H0    3072                    // 128*128*4 = 65536
#define SOFF_H1    68608
#define SMEM_TOTAL 134144

// ---------------- scratch ----------------
__device__ float g_denom[1048576];
__device__ int   g_is64;

__device__ __forceinline__ int getb(const void* bp, int i) {
    if (g_is64) return (int)((const long long*)bp)[i];
    return ((const int*)bp)[i];
}

// bf16 2-term split of a float pair: hp = {bf16(x1):bf16(x0)}, lp = residuals
__device__ __forceinline__ void split2(float x0, float x1, uint32_t& hp, uint32_t& lp) {
    asm("cvt.rn.bf16x2.f32 %0, %1, %2;" : "=r"(hp) : "f"(x1), "f"(x0));
    float h0 = __uint_as_float(hp << 16);
    float h1 = __uint_as_float(hp & 0xFFFF0000u);
    float l0 = x0 - h0;
    float l1 = x1 - h1;
    asm("cvt.rn.bf16x2.f32 %0, %1, %2;" : "=r"(lp) : "f"(l1), "f"(l0));
}

__device__ __forceinline__ void mma16(float* d, const uint32_t* a, uint32_t b0, uint32_t b1) {
    asm("mma.sync.aligned.m16n8k16.row.col.f32.bf16.bf16.f32 "
        "{%0,%1,%2,%3}, {%4,%5,%6,%7}, {%8,%9}, {%0,%1,%2,%3};"
        : "+f"(d[0]), "+f"(d[1]), "+f"(d[2]), "+f"(d[3])
        : "r"(a[0]), "r"(a[1]), "r"(a[2]), "r"(a[3]), "r"(b0), "r"(b1));
}

__device__ __forceinline__ float ftanh(float x) {
    float e2 = __expf(2.f * x);
    return 1.f - __fdividef(2.f, e2 + 1.f);
}

// ---------------- kdetect: batch dtype ----------------
__global__ void kdetect(const void* __restrict__ batch, int N, int G) {
    __shared__ int bad;
    if (threadIdx.x == 0) bad = 0;
    __syncthreads();
    const long long* b64 = (const long long*)batch;
    int half = N >> 1;
    int last = (half > 1) ? (half - 1) : 0;
    for (int t = threadIdx.x; t < 2048; t += 256) {
        long long idx = (long long)t * last / 2047;
        long long v = b64[idx];
        if (v < 0 || v >= (long long)G) bad = 1;
    }
    __syncthreads();
    if (threadIdx.x == 0) g_is64 = bad ? 0 : 1;
}

// ---------------- k0: zero out + denom ----------------
__global__ void k0(float* __restrict__ out, int outSize, int G) {
    int i = blockIdx.x * blockDim.x + threadIdx.x;
    if (i < outSize) out[i] = 0.f;
    if (i < G) g_denom[i] = 0.f;
}

// ---------------- fused: bf16x3 mma GEMM + tanh + score + exp + segment scatter ----------------
__global__ __launch_bounds__(256, 1)
void kfused(const float* __restrict__ H, const float* __restrict__ w1,
            const float* __restrict__ w2, const void* __restrict__ batch,
            float* __restrict__ out, int N) {
    extern __shared__ char smem[];
    float* spart = (float*)(smem + SOFF_SPART);   // [4][128]
    float* cf    = (float*)(smem + SOFF_CF);      // [128] numerators e
    int*   sg    = (int*)(smem + SOFF_SG);        // [128] segment ids

    const int tid   = threadIdx.x;
    const int w     = tid >> 5;
    const int lane  = tid & 31;
    const int g     = lane >> 2;         // group 0..7
    const int c     = lane & 3;          // thread-in-group
    const int wsl   = w & 3;             // hid slice (16 hid rows)
    const int ogrp  = (w >> 2) * 8;      // octet base
    const int m8    = (g & 3) << 3;      // row-XOR swizzle constant (floats)

    // ---- A = w1 fragments (bf16 hi/lo), resident for whole kernel ----
    uint32_t Ah[8][4], Al[8][4];
    {
        const int r0 = (16 * wsl + g) * IN_DIM;
        const int r1 = r0 + 8 * IN_DIM;
#pragma unroll
        for (int j = 0; j < 8; ++j) {
            int kb = 16 * j + 2 * c;
            split2(__ldg(&w1[r0 + kb]),     __ldg(&w1[r0 + kb + 1]), Ah[j][0], Al[j][0]);
            split2(__ldg(&w1[r1 + kb]),     __ldg(&w1[r1 + kb + 1]), Ah[j][1], Al[j][1]);
            split2(__ldg(&w1[r0 + kb + 8]), __ldg(&w1[r0 + kb + 9]), Ah[j][2], Al[j][2]);
            split2(__ldg(&w1[r1 + kb + 8]), __ldg(&w1[r1 + kb + 9]), Ah[j][3], Al[j][3]);
        }
    }
    const float w2a = __ldg(&w2[16 * wsl + g]);
    const float w2b = __ldg(&w2[16 * wsl + g + 8]);

    const long long T = ((long long)N + TILE_M - 1) / TILE_M;
    long long t = blockIdx.x;
    int buf = 0;

    // cp.async prefetch with XOR swizzle: float col k of row r stored at k ^ (8*(r&3))
    auto prefetch = [&](long long tt, int bsel) {
        const char* base = (const char*)H + (unsigned long long)tt * TILE_M * IN_DIM * 4ull;
        char* dstb = smem + (bsel ? SOFF_H1 : SOFF_H0);
#pragma unroll
        for (int it = 0; it < 16; ++it) {
            int idx = it * 256 + tid;
            int row = idx >> 5, c4 = idx & 31;
            long long gn = tt * TILE_M + row;
            int colf = (4 * c4) ^ ((row & 3) << 3);
            uint32_t d;
            asm("{ .reg .u64 tt; cvta.to.shared.u64 tt, %1; cvt.u32.u64 %0, tt; }"
                : "=r"(d) : "l"(dstb + row * 512 + colf * 4));
            const char* s = base + (row * 512 + c4 * 16);
            int sz = (gn < N) ? 16 : 0;
            asm volatile("cp.async.cg.shared.global [%0], [%1], 16, %2;"
                         :: "r"(d), "l"(s), "r"(sz) : "memory");
        }
        asm volatile("cp.async.commit_group;" ::: "memory");
    };

    if (t < T) prefetch(t, 0);

    for (; t < T; t += gridDim.x) {
        asm volatile("cp.async.wait_group 0;" ::: "memory");
        __syncthreads();
        long long tn = t + gridDim.x;
        if (tn < T) prefetch(tn, buf ^ 1);

        const float* Hs = (const float*)(smem + (buf ? SOFF_H1 : SOFF_H0));

        // ---- per octet: 24 mma across 3 independent accumulator chains ----
#pragma unroll 1
        for (int o = 0; o < 8; ++o) {
            const int oct = ogrp + o;
            const float* hb = Hs + (8 * oct + g) * IN_DIM;
            float accA[4] = {0.f, 0.f, 0.f, 0.f};
            float accB[4] = {0.f, 0.f, 0.f, 0.f};
            float accC[4] = {0.f, 0.f, 0.f, 0.f};
#pragma unroll
            for (int j = 0; j < 8; ++j) {
                int k0 = (16 * j + 2 * c) ^ m8;
                int k1 = (16 * j + 2 * c + 8) ^ m8;
                float2 v0 = *(const float2*)(hb + k0);
                float2 v1 = *(const float2*)(hb + k1);
                uint32_t b0h, b0l, b1h, b1l;
                split2(v0.x, v0.y, b0h, b0l);
                split2(v1.x, v1.y, b1h, b1l);
                mma16(accA, Ah[j], b0h, b1h);
                mma16(accB, Al[j], b0h, b1h);
                mma16(accC, Ah[j], b0l, b1l);
            }
            float d0 = accA[0] + accB[0] + accC[0];
            float d1 = accA[1] + accB[1] + accC[1];
            float d2 = accA[2] + accB[2] + accC[2];
            float d3 = accA[3] + accB[3] + accC[3];
            // partial s: this thread's 2 hid rows, nodes 2c (even) / 2c+1 (odd)
            float pe = fmaf(w2a, ftanh(d0), w2b * ftanh(d2));
            float po = fmaf(w2a, ftanh(d1), w2b * ftanh(d3));
#pragma unroll
            for (int m = 4; m <= 16; m <<= 1) {
                pe += __shfl_xor_sync(0xffffffffu, pe, m);
                po += __shfl_xor_sync(0xffffffffu, po, m);
            }
            if (g == 0) {
                spart[wsl * 128 + oct * 8 + 2 * c]     = pe;
                spart[wsl * 128 + oct * 8 + 2 * c + 1] = po;
            }
        }
        __syncthreads();

        // ---- combine hid slices, e = exp(s) (no max-sub: |s| bounded), denom ----
        if (tid < 128) {
            long long gn = t * TILE_M + tid;
            bool act = gn < N;
            float s = spart[tid] + spart[128 + tid] + spart[256 + tid] + spart[384 + tid];
            int bi = act ? (int)gn : (N - 1);
            int b = getb(batch, bi);
            float e = act ? __expf(s) : 0.f;
            cf[tid] = e;
            sg[tid] = b;
            float es = e;
#pragma unroll
            for (int d = 1; d < 32; d <<= 1) {
                float v  = __shfl_down_sync(0xffffffffu, es, d);
                int   b2 = __shfl_down_sync(0xffffffffu, b, d);
                if ((lane + d) < 32 && b2 == b) es += v;
            }
            int bprev = __shfl_up_sync(0xffffffffu, b, 1);
            if (lane == 0 || bprev != b) atomicAdd(&g_denom[b], es);
        }
        __syncthreads();

        // ---- scatter: 4 groups x 32 nodes; thread handles feature pair ----
        {
            const int q    = tid >> 6;
            const int f2   = tid & 63;
            const int base = 32 * q;
            int cur = sg[base];
            float ax = 0.f, ay = 0.f;
#pragma unroll 4
            for (int j = 0; j < 32; ++j) {
                int bj = sg[base + j];
                if (bj != cur) {
                    float* o = &out[(size_t)cur * IN_DIM + 2 * f2];
                    atomicAdd(o,     ax);
                    atomicAdd(o + 1, ay);
                    ax = 0.f; ay = 0.f;
                    cur = bj;
                }
                float2 h = *(const float2*)(Hs + (base + j) * IN_DIM
                                            + ((2 * f2) ^ ((j & 3) << 3)));
                float cc = cf[base + j];
                ax = fmaf(cc, h.x, ax);
                ay = fmaf(cc, h.y, ay);
            }
            float* o = &out[(size_t)cur * IN_DIM + 2 * f2];
            atomicAdd(o,     ax);
            atomicAdd(o + 1, ay);
        }
        buf ^= 1;
    }
}

// ---------------- final divide ----------------
__global__ void kfin(float* __restrict__ out, int outSize) {
    int i = blockIdx.x * blockDim.x + threadIdx.x;
    if (i < outSize) {
        float d = g_denom[i >> 7];
        out[i] = (d > 0.f) ? out[i] / d : 0.f;
    }
}

// ---------------- launch ----------------
extern "C" void kernel_launch(void* const* d_in, const int* in_sizes, int n_in,
                              void* d_out, int out_size) {
    const float* H  = (const float*)d_in[0];
    const float* w1 = (const float*)d_in[1];
    const float* w2 = (const float*)d_in[2];
    const void*  batch = d_in[3];
    int N = in_sizes[0] / IN_DIM;
    int G = out_size / IN_DIM;
    float* out = (float*)d_out;

    int sms = 148;
    cudaDeviceGetAttribute(&sms, cudaDevAttrMultiProcessorCount, 0);

    cudaFuncSetAttribute(kfused, cudaFuncAttributeMaxDynamicSharedMemorySize, SMEM_TOTAL);

    kdetect<<<1, 256>>>(batch, N, G);
    int initN = out_size > G ? out_size : G;
    k0<<<(initN + 255) / 256, 256>>>(out, out_size, G);
    kfused<<<sms, 256, SMEM_TOTAL>>>(H, w1, w2, batch, out, N);
    kfin<<<(out_size + 255) / 256, 256>>>(out, out_size);
}